// round 2
// baseline (speedup 1.0000x reference)
#include <cuda_runtime.h>

// Problem constants
#define N_ZQ   2097152   // 8*64*64*64 z_q elements (also input element count)
#define N_IDX  32768     // 8*64*64 index entries
#define K_ROWS 8192
#define D_DIM  64
#define MAIN_BLOCKS 592
#define N_F4   (N_ZQ / 4)

// Scratch (no device allocation allowed) — fully overwritten every launch,
// so graph replays are deterministic.
__device__ unsigned long long g_amin[32];
__device__ double g_losspart[MAIN_BLOCKS];

// ---------------------------------------------------------------------------
// Kernel 1: per-row squared norm of book, packed argmin partials.
// 32 blocks x 256 threads = 8192 threads, one book row each (256B contiguous
// per thread via float4 -> full line utilization).
// Positive-float bit pattern is monotone, so (norm_bits<<32)|row gives min
// norm with first-index tie-break under u64 min.
// ---------------------------------------------------------------------------
__global__ void k_argmin(const float* __restrict__ book) {
    __shared__ unsigned long long s[256];
    int r = blockIdx.x * 256 + threadIdx.x;   // 0..8191
    const float4* b4 = reinterpret_cast<const float4*>(book) + (size_t)r * 16;
    float acc = 0.0f;
#pragma unroll
    for (int i = 0; i < 16; ++i) {
        float4 v = b4[i];
        acc = fmaf(v.x, v.x, acc);
        acc = fmaf(v.y, v.y, acc);
        acc = fmaf(v.z, v.z, acc);
        acc = fmaf(v.w, v.w, acc);
    }
    unsigned long long key =
        ((unsigned long long)__float_as_uint(acc) << 32) | (unsigned)r;
    s[threadIdx.x] = key;
    __syncthreads();
#pragma unroll
    for (int off = 128; off > 0; off >>= 1) {
        if (threadIdx.x < off) {
            unsigned long long o = s[threadIdx.x + off];
            if (o < s[threadIdx.x]) s[threadIdx.x] = o;
        }
        __syncthreads();
    }
    if (threadIdx.x == 0) g_amin[blockIdx.x] = s[0];
}

// ---------------------------------------------------------------------------
// Kernel 2: fused main.
//  - every block redundantly reduces the 32 argmin partials (cheap)
//  - loads book[k*] (64 floats) into smem
//  - grid-stride over float4s: read input (loss), write z_q, fill idx
//  - per-block loss partial (double) to scratch, no atomics
// ---------------------------------------------------------------------------
__global__ void k_main(const float* __restrict__ in,
                       const float* __restrict__ book,
                       float* __restrict__ out, int out_size) {
    __shared__ float sbk[D_DIM];
    __shared__ unsigned long long sm[32];
    __shared__ int skmin;
    __shared__ float swr[8];

    int t = threadIdx.x;
    if (t < 32) sm[t] = g_amin[t];
    __syncthreads();
    if (t < 32) {
        unsigned long long v = sm[t];
#pragma unroll
        for (int off = 16; off > 0; off >>= 1) {
            unsigned long long o = __shfl_down_sync(0xffffffffu, v, off);
            if (o < v) v = o;
        }
        if (t == 0) skmin = (int)(v & 0xffffffffu);
    }
    __syncthreads();
    int kmin = skmin;
    if (t < D_DIM) sbk[t] = book[(size_t)kmin * D_DIM + t];
    __syncthreads();

    int gtid   = blockIdx.x * blockDim.x + t;
    int stride = gridDim.x * blockDim.x;

    const float4* in4  = reinterpret_cast<const float4*>(in);
    float4*       out4 = reinterpret_cast<float4*>(out);

    float lsum = 0.0f;
    for (int j = gtid; j < N_F4; j += stride) {
        float4 x = in4[j];
        int w0 = (j << 2) & 63;               // w index of x.x
        float d0 = sbk[w0]     - x.x;
        float d1 = sbk[w0 + 1] - x.y;
        float d2 = sbk[w0 + 2] - x.z;
        float d3 = sbk[w0 + 3] - x.w;
        lsum = fmaf(d0, d0, lsum);
        lsum = fmaf(d1, d1, lsum);
        lsum = fmaf(d2, d2, lsum);
        lsum = fmaf(d3, d3, lsum);
        // z_q output at same flat position: value depends only on (i>>12)&63
        float v = sbk[(j >> 10) & 63];        // (4j >> 12) & 63
        out4[j] = make_float4(v, v, v, v);
    }

    // idx section (as float values of the constant argmin index)
    if (out_size >= N_ZQ + N_IDX) {
        float fk = (float)kmin;
        for (int j = gtid; j < N_IDX; j += stride) out[N_ZQ + j] = fk;
    }

    // block-reduce loss partial
#pragma unroll
    for (int off = 16; off > 0; off >>= 1)
        lsum += __shfl_down_sync(0xffffffffu, lsum, off);
    if ((t & 31) == 0) swr[t >> 5] = lsum;
    __syncthreads();
    if (t == 0) {
        double s = 0.0;
#pragma unroll
        for (int i = 0; i < 8; ++i) s += (double)swr[i];
        g_losspart[blockIdx.x] = s;
    }
}

// ---------------------------------------------------------------------------
// Kernel 3: finalize loss = 1.25 * mean of squared diffs.
// ---------------------------------------------------------------------------
__global__ void k_fin(float* __restrict__ out, int out_size) {
    if (threadIdx.x == 0 && out_size >= N_ZQ + N_IDX + 1) {
        double s = 0.0;
        for (int i = 0; i < MAIN_BLOCKS; ++i) s += g_losspart[i];
        out[N_ZQ + N_IDX] = (float)(1.25 * s / (double)N_ZQ);
    }
}

extern "C" void kernel_launch(void* const* d_in, const int* in_sizes, int n_in,
                              void* d_out, int out_size) {
    const float* input = (const float*)d_in[0];
    const float* book  = (const float*)d_in[1];
    // Defensive: swap if metadata order is (book, input)
    if (n_in >= 2 && in_sizes[0] == K_ROWS * D_DIM && in_sizes[1] == N_ZQ) {
        const float* tmp = input; input = book; book = tmp;
    }
    float* out = (float*)d_out;

    k_argmin<<<32, 256>>>(book);
    k_main<<<MAIN_BLOCKS, 256>>>(input, book, out, out_size);
    k_fin<<<1, 32>>>(out, out_size);
}

// round 3
// speedup vs baseline: 2.8870x; 2.8870x over previous
#include <cuda_runtime.h>

// Problem constants
#define N_ZQ   2097152   // 8*64*64*64 z_q elements (also input element count)
#define N_IDX  32768     // 8*64*64 index entries
#define K_ROWS 8192
#define D_DIM  64
#define AMIN_BLOCKS 128
#define MAIN_BLOCKS 512
#define N_F4   (N_ZQ / 4)        // 524288 = 512*256*4 exactly

// Scratch (no device allocation allowed) — fully overwritten every launch.
__device__ unsigned long long g_amin[AMIN_BLOCKS];
__device__ double g_losspart[MAIN_BLOCKS];

// ---------------------------------------------------------------------------
// Kernel 1: book row norms + packed argmin partials.
// 128 blocks x 256 threads = 32768 threads; 4 threads per row, 16 floats each.
// Lanes {4r, 4r+1, 4r+2, 4r+3} share a row -> shfl-xor butterfly over 1,2
// gives every lane the full row norm. Positive-float bits are monotone, so
// (norm_bits<<32)|row under u64-min = argmin with first-index tie-break.
// ---------------------------------------------------------------------------
__global__ void k_argmin(const float* __restrict__ book) {
    __shared__ unsigned long long s[256];
    int g = blockIdx.x * 256 + threadIdx.x;      // 0..32767
    int r = g >> 2;                              // row 0..8191
    int q = g & 3;                               // quarter within row
    const float4* b4 = reinterpret_cast<const float4*>(book) + (size_t)r * 16 + q * 4;
    float acc = 0.0f;
#pragma unroll
    for (int i = 0; i < 4; ++i) {
        float4 v = b4[i];
        acc = fmaf(v.x, v.x, acc);
        acc = fmaf(v.y, v.y, acc);
        acc = fmaf(v.z, v.z, acc);
        acc = fmaf(v.w, v.w, acc);
    }
    // butterfly within the 4-lane row group
    acc += __shfl_xor_sync(0xffffffffu, acc, 1);
    acc += __shfl_xor_sync(0xffffffffu, acc, 2);
    unsigned long long key =
        ((unsigned long long)__float_as_uint(acc) << 32) | (unsigned)r;
    s[threadIdx.x] = key;
    __syncthreads();
#pragma unroll
    for (int off = 128; off > 0; off >>= 1) {
        if (threadIdx.x < off) {
            unsigned long long o = s[threadIdx.x + off];
            if (o < s[threadIdx.x]) s[threadIdx.x] = o;
        }
        __syncthreads();
    }
    if (threadIdx.x == 0) g_amin[blockIdx.x] = s[0];
}

// ---------------------------------------------------------------------------
// Kernel 2: fused main.
//  - every block reduces the 128 argmin partials (shared tree, cheap)
//  - loads book[k*] (64 floats) into smem
//  - exact-fit loop: 4 float4s per thread (512*256*4 == N_F4), no tail
//  - per-block loss partial (double) to scratch, no atomics
// ---------------------------------------------------------------------------
__global__ void k_main(const float* __restrict__ in,
                       const float* __restrict__ book,
                       float* __restrict__ out, int out_size) {
    __shared__ float sbk[D_DIM];
    __shared__ unsigned long long sm[AMIN_BLOCKS];
    __shared__ float swr[8];

    int t = threadIdx.x;
    if (t < AMIN_BLOCKS) sm[t] = g_amin[t];
    __syncthreads();
#pragma unroll
    for (int off = AMIN_BLOCKS / 2; off > 0; off >>= 1) {
        if (t < off) {
            unsigned long long o = sm[t + off];
            if (o < sm[t]) sm[t] = o;
        }
        __syncthreads();
    }
    int kmin = (int)(sm[0] & 0xffffffffu);
    if (t < D_DIM) sbk[t] = book[(size_t)kmin * D_DIM + t];
    __syncthreads();

    int gtid   = blockIdx.x * 256 + t;
    const int stride = MAIN_BLOCKS * 256;

    const float4* in4  = reinterpret_cast<const float4*>(in);
    float4*       out4 = reinterpret_cast<float4*>(out);

    float lsum = 0.0f;
#pragma unroll
    for (int k = 0; k < 4; ++k) {
        int j = gtid + k * stride;
        float4 x = in4[j];
        int w0 = (j << 2) & 63;               // w index of x.x
        float d0 = sbk[w0]     - x.x;
        float d1 = sbk[w0 + 1] - x.y;
        float d2 = sbk[w0 + 2] - x.z;
        float d3 = sbk[w0 + 3] - x.w;
        lsum = fmaf(d0, d0, lsum);
        lsum = fmaf(d1, d1, lsum);
        lsum = fmaf(d2, d2, lsum);
        lsum = fmaf(d3, d3, lsum);
        // z_q value at this flat position depends only on (4j>>12)&63
        float v = sbk[(j >> 10) & 63];
        out4[j] = make_float4(v, v, v, v);
    }

    // idx section: vectorized constant fill (first 8192 threads, one float4 each)
    if (out_size >= N_ZQ + N_IDX && gtid < N_IDX / 4) {
        float fk = (float)kmin;
        out4[N_ZQ / 4 + gtid] = make_float4(fk, fk, fk, fk);
    }

    // block-reduce loss partial
#pragma unroll
    for (int off = 16; off > 0; off >>= 1)
        lsum += __shfl_down_sync(0xffffffffu, lsum, off);
    if ((t & 31) == 0) swr[t >> 5] = lsum;
    __syncthreads();
    if (t == 0) {
        double s = 0.0;
#pragma unroll
        for (int i = 0; i < 8; ++i) s += (double)swr[i];
        g_losspart[blockIdx.x] = s;
    }
}

// ---------------------------------------------------------------------------
// Kernel 3: parallel loss finalize. 256 threads, shared double tree reduce —
// replaces the old single-thread 592-deep FP64 dependency chain (~19us).
// ---------------------------------------------------------------------------
__global__ void k_fin(float* __restrict__ out, int out_size) {
    __shared__ double sd[256];
    int t = threadIdx.x;
    double s = g_losspart[t] + g_losspart[t + 256];   // MAIN_BLOCKS = 512
    sd[t] = s;
    __syncthreads();
#pragma unroll
    for (int off = 128; off > 0; off >>= 1) {
        if (t < off) sd[t] += sd[t + off];
        __syncthreads();
    }
    if (t == 0 && out_size >= N_ZQ + N_IDX + 1)
        out[N_ZQ + N_IDX] = (float)(1.25 * sd[0] / (double)N_ZQ);
}

extern "C" void kernel_launch(void* const* d_in, const int* in_sizes, int n_in,
                              void* d_out, int out_size) {
    const float* input = (const float*)d_in[0];
    const float* book  = (const float*)d_in[1];
    // Defensive: swap if metadata order is (book, input)
    if (n_in >= 2 && in_sizes[0] == K_ROWS * D_DIM && in_sizes[1] == N_ZQ) {
        const float* tmp = input; input = book; book = tmp;
    }
    float* out = (float*)d_out;

    k_argmin<<<AMIN_BLOCKS, 256>>>(book);
    k_main<<<MAIN_BLOCKS, 256>>>(input, book, out, out_size);
    k_fin<<<1, 256>>>(out, out_size);
}